// round 11
// baseline (speedup 1.0000x reference)
#include <cuda_runtime.h>
#include <cuda_bf16.h>
#include <math.h>

#define D_    256
#define NB    64
#define SEQ   1024
#define EPSV  1e-10f
#define NIT   12
#define NROUNDS 7          // multisection rounds, 9x contraction each

// closed-form constants
#define ALPHA     0.32768f        // (1-2*ETA)^5
#define ALPHA2_64 0.0016777216f   // ALPHA^2 / 64
#define ALPHA_8   0.04096f        // ALPHA / 8
#define BETA      0.59049f        // (1-ETA)^5
#define OMBETA    0.40951f        // 1 - BETA

#define BAR64() asm volatile("bar.sync 1, 64;" ::: "memory")

// ---------------- device scratch (no allocations allowed) ----------------
__device__ float g_D0[NB * D_];         // deviations
__device__ float g_Gg[NB * NB];         // Gram matrix
__device__ float g_Wg[NB * NB];         // eigenvectors of G (columns, ascending)
__device__ float g_UT[NB * D_];         // UT[k][d]: eigvec k of A (63 used)
__device__ float g_poles[NB];           // poles[0]=0, poles[1..63] ascending
__device__ float g_trA;                 // sum of kept poles
__device__ float g_M[SEQ * D_];         // m_t per step

// ------ 1) fused scan (32 blocks) + gram (64 blocks)  <<<96,256>>> -------
__global__ void k_scan_gram(const int* __restrict__ tokens,
                            const float* __restrict__ embed,
                            const float* __restrict__ bubbles,
                            const float* __restrict__ mdecay) {
    __shared__ float rowi[D_];
    __shared__ float bmsh[D_];
    __shared__ int   tk[128];
    int t = threadIdx.x;

    if (blockIdx.x < 64) {
        // ---- gram block i: G[i][*] = (a^2/64) D0_i . D0_j ----
        int i = blockIdx.x;
        float s = 0.f;
#pragma unroll 8
        for (int r = 0; r < NB; r++) s += bubbles[r * D_ + t];
        float bm = s * (1.f / NB);
        float v = bubbles[i * D_ + t] - bm;
        rowi[t] = v;
        bmsh[t] = bm;
        g_D0[i * D_ + t] = v;
        __syncthreads();

        int lane = t & 31, w = t >> 5;
#pragma unroll
        for (int it = 0; it < 8; it++) {
            int j = w * 8 + it;
            const float* bj = bubbles + j * D_;
            float acc = 0.f;
#pragma unroll
            for (int m = 0; m < 8; m++) {
                int d = lane + 32 * m;
                acc += rowi[d] * (bj[d] - bmsh[d]);
            }
#pragma unroll
            for (int o = 16; o > 0; o >>= 1)
                acc += __shfl_down_sync(0xFFFFFFFFu, acc, o);
            if (lane == 0) g_Gg[i * NB + j] = acc * ALPHA2_64;
        }
    } else {
        // ---- scan block: contraction a ~ 0.778, a^96 ~ 3e-11 warmup ----
        int c = blockIdx.x - 64, d = t;
        float s0 = 0.f, s1 = 0.f;
#pragma unroll 8
        for (int r = 0; r < NB; r += 2) {
            s0 += bubbles[r * D_ + d];
            s1 += bubbles[(r + 1) * D_ + d];
        }
        float cb = BETA * (s0 + s1) * (1.f / NB);
        float decay = 1.f / (1.f + expf(-mdecay[0]));
        float omdecay = 1.f - decay;

        int tout = c * 32;
        int tstart = tout - 96; if (tstart < 0) tstart = 0;
        int tend = tout + 32;
        int nwin = tend - tstart;
        if (d < nwin) tk[d] = tokens[tstart + d];
        __syncthreads();

        float mm = 0.f;
        float xs[8];
#pragma unroll
        for (int j = 0; j < 8; j++) xs[j] = embed[(long)tk[j] * D_ + d];
        for (int t0 = tstart; t0 < tend; t0 += 8) {
#pragma unroll
            for (int j = 0; j < 8; j++) {
                int tt = t0 + j;
                float x = xs[j];
                int tn = t0 + 8 + j;
                if (tn < tend) xs[j] = embed[(long)tk[tn - tstart] * D_ + d];
                float m = cb + OMBETA * (x + decay * mm);
                if (tt >= tout) g_M[tt * D_ + d] = m;
                mm = decay * mm + omdecay * m;
            }
        }
    }
}

// ------ 2) fused eigensolver: tridiag + Sturm + invit + backtransform ----
__global__ void __launch_bounds__(1024, 1) k_eigen() {  // <<<1,1024,66560>>>
    extern __shared__ float sm[];
    float* E  = sm;                   // 64x65 eigvec columns
    float* DD = sm + 4160;            // invit scratch
    float* YY = sm + 8320;            // invit scratch
    float* V  = sm + 12480;           // reflectors [k][r], pitch 65

    __shared__ float diag[64], off[64], b2[64], eig[64], tauv[64];
    __shared__ float vsh[64], wsh[64];
    __shared__ float red[32];
    __shared__ int   oflag[64];
    __shared__ float sc_lo, sc_hi;

    int tid = threadIdx.x, lane = tid & 31, warp = tid >> 5;

    // ---- phase T: register/spill Householder tridiag (threads 0..63) ----
    if (tid < 64) {
        float row[NB];
        int r = tid;
#pragma unroll
        for (int c = 0; c < NB; c++) row[c] = g_Gg[r * NB + c];
        float x = row[0];

#pragma unroll 1
        for (int k = 0; k < 62; k++) {
            int n0 = k + 1;
            float xm = (r >= n0) ? x : 0.f;
            float s = xm * xm;
#pragma unroll
            for (int o = 16; o > 0; o >>= 1)
                s += __shfl_xor_sync(0xFFFFFFFFu, s, o);
            if (lane == 0) red[warp] = s;
            if (r == n0) red[2] = xm;
            BAR64();
            float sum = red[0] + red[1];
            float x0 = red[2];
            float sigma = sqrtf(sum);
            float sgn = (x0 >= 0.f) ? 1.f : -1.f;
            float tau = (sum > 1e-30f)
                      ? __fdividef(1.f, sigma * (sigma + fabsf(x0))) : 0.f;
            if (r == 0) { off[k] = -sgn * sigma; tauv[k] = tau; }
            float v = (r == n0) ? x0 + sgn * sigma : xm;   // xm==0 for r<n0
            vsh[r] = v;
            V[k * 65 + r] = v;
            BAR64();
            float a0 = 0.f, a1 = 0.f, a2 = 0.f, a3 = 0.f;
#pragma unroll
            for (int c = 0; c < NB; c += 4) {
                a0 += row[c]     * vsh[c];
                a1 += row[c + 1] * vsh[c + 1];
                a2 += row[c + 2] * vsh[c + 2];
                a3 += row[c + 3] * vsh[c + 3];
            }
            float p = tau * ((a0 + a1) + (a2 + a3));
            float pv = p * v;
#pragma unroll
            for (int o = 16; o > 0; o >>= 1)
                pv += __shfl_xor_sync(0xFFFFFFFFu, pv, o);
            if (lane == 0) red[warp] = pv;
            BAR64();
            float K = 0.5f * tau * (red[0] + red[1]);
            float w = (r >= n0) ? (p - K * v) : 0.f;
            wsh[r] = w;
            BAR64();
            float xn = x;
#pragma unroll
            for (int c = 0; c < NB; c++) {
                float nv = row[c] - v * wsh[c] - w * vsh[c];
                row[c] = nv;
                if (c == n0) xn = nv;
            }
            x = xn;
        }

        float dg = 0.f;
#pragma unroll
        for (int c = 0; c < NB; c++) if (c == r) dg = row[c];
        diag[r] = dg;
        if (r == 63) off[62] = row[62];
        if (r == 0)  off[63] = 0.f;
    }
    __syncthreads();   // all 1024 threads join here

    if (tid < 63) b2[tid] = off[tid] * off[tid];
    if (tid == 0) {
        float lo = 1e30f, hi = -1e30f;
        for (int i = 0; i < 64; i++) {
            float om = (i > 0) ? fabsf(off[i - 1]) : 0.f;
            float op = (i < 63) ? fabsf(off[i]) : 0.f;
            lo = fminf(lo, diag[i] - om - op);
            hi = fmaxf(hi, diag[i] + om + op);
        }
        float mg = 1e-6f * fmaxf(fabsf(lo), fabsf(hi)) + 1e-30f;
        sc_lo = lo - mg; sc_hi = hi + mg;
    }
    __syncthreads();

    // ---- multisection Sturm: 8 threads per eigenvalue ----
    if (tid < 512) {
        int i = tid >> 3, s8 = tid & 7;
        float lo = sc_lo, hi = sc_hi;
        for (int round = 0; round < NROUNDS; round++) {
            float step = (hi - lo) * (1.f / 9.f);
            float mid = lo + step * (float)(s8 + 1);
            float d = diag[0] - mid;
            int cnt = (d < 0.f);
            for (int j = 1; j < 64; j++) {
                float dg = (fabsf(d) < 1e-25f) ? -1e-25f : d;
                d = (diag[j] - mid) - __fdividef(b2[j - 1], dg);
                cnt += (d < 0.f);
            }
            unsigned bal = __ballot_sync(0xFFFFFFFFu, cnt <= i);
            unsigned bits = (bal >> (lane & 24)) & 0xFFu;
            int p = __popc(bits);
            lo = lo + step * (float)p;
            hi = lo + step;
        }
        if (s8 == 0) eig[i] = 0.5f * (lo + hi);
    }
    __syncthreads();

    // ---- inverse iteration ----
    if (tid < 64) {
        int i = tid;
        float scale = fmaxf(fabsf(sc_hi), fabsf(sc_lo));
        float lam = eig[i] + scale * 2e-6f;
        unsigned h = (unsigned)(i * 2654435761u) ^ 0x9E3779B9u;
        for (int j = 0; j < 64; j++) {
            h = h * 1664525u + 1013904223u;
            E[j * 65 + i] = 1.f + (float)(h >> 16) * 1.52587890625e-05f;
        }
        for (int iter = 0; iter < 3; iter++) {
            float dprev = diag[0] - lam;
            dprev = (fabsf(dprev) < 1e-20f) ? copysignf(1e-20f, dprev) : dprev;
            DD[i * 65 + 0] = dprev;
            float yprev = E[0 * 65 + i];
            YY[i * 65 + 0] = yprev;
            for (int j = 1; j < 64; j++) {
                float m = __fdividef(off[j - 1], dprev);
                float dcur = (diag[j] - lam) - m * off[j - 1];
                dcur = (fabsf(dcur) < 1e-20f) ? copysignf(1e-20f, dcur) : dcur;
                float ycur = E[j * 65 + i] - m * yprev;
                DD[i * 65 + j] = dcur;
                YY[i * 65 + j] = ycur;
                dprev = dcur; yprev = ycur;
            }
            float vj = __fdividef(YY[i * 65 + 63], DD[i * 65 + 63]);
            E[63 * 65 + i] = vj;
            float nrm = vj * vj;
            for (int j = 62; j >= 0; j--) {
                vj = __fdividef(YY[i * 65 + j] - off[j] * vj, DD[i * 65 + j]);
                E[j * 65 + i] = vj;
                nrm += vj * vj;
            }
            float inv = rsqrtf(nrm);
            for (int j = 0; j < 64; j++) E[j * 65 + i] *= inv;
        }
    }
    __syncthreads();

    // ---- gap-flagged neighbor re-orthogonalization ----
    if (tid < 64) {
        float scale = fmaxf(fabsf(eig[63]), fabsf(eig[0]));
        oflag[tid] = (tid > 0) && (eig[tid] - eig[tid - 1] < 1e-3f * scale);
    }
    __syncthreads();
    for (int i = 1; i < 64; i++) {
        if (!oflag[i]) continue;
        float pr = (tid < 64) ? E[tid * 65 + i] * E[tid * 65 + i - 1] : 0.f;
#pragma unroll
        for (int o = 16; o > 0; o >>= 1)
            pr += __shfl_down_sync(0xFFFFFFFFu, pr, o);
        if (lane == 0 && tid < 64) red[warp] = pr;
        __syncthreads();
        float dot = red[0] + red[1];
        float nv = 0.f;
        if (tid < 64) {
            E[tid * 65 + i] -= dot * E[tid * 65 + i - 1];
            nv = E[tid * 65 + i] * E[tid * 65 + i];
        }
#pragma unroll
        for (int o = 16; o > 0; o >>= 1)
            nv += __shfl_down_sync(0xFFFFFFFFu, nv, o);
        if (lane == 0 && tid < 64) red[warp] = nv;
        __syncthreads();
        float sc = rsqrtf(red[0] + red[1] + 1e-30f);
        if (tid < 64) E[tid * 65 + i] *= sc;
        __syncthreads();
    }

    // ---- back-transform: apply reflectors k = 61..0 (cols independent) --
    {
        int col = tid >> 4, sub = tid & 15;
        for (int k = 61; k >= 0; k--) {
            int n0 = k + 1, n2 = 63 - k;
            float tau = tauv[k];
            float acc = 0.f;
            for (int r = sub; r < n2; r += 16)
                acc += V[k * 65 + n0 + r] * E[(n0 + r) * 65 + col];
#pragma unroll
            for (int o = 8; o > 0; o >>= 1)
                acc += __shfl_xor_sync(0xFFFFFFFFu, acc, o, 16);
            float w = tau * acc;
            for (int r = sub; r < n2; r += 16)
                E[(n0 + r) * 65 + col] -= w * V[k * 65 + n0 + r];
        }
    }
    __syncthreads();

    if (tid == 0) {
        g_poles[0] = 0.f;
        float s = 0.f;
        for (int k = 1; k < 64; k++) {
            float p = fmaxf(eig[k], 1e-12f);
            g_poles[k] = p;
            s += p;
        }
        g_trA = s;
    }
    for (int e = tid; e < NB * NB; e += 1024)
        g_Wg[e] = E[(e >> 6) * 65 + (e & 63)];
}

// ------ 3) build U^T  <<<63,256>>>  (full unroll -> deep MLP) ------------
__global__ void k_buildU() {
    __shared__ float wcol[NB];
    int k = blockIdx.x, d = threadIdx.x;
    if (d < NB) wcol[d] = g_Wg[d * NB + (k + 1)];   // ascending columns
    __syncthreads();
    float acc = 0.f;
#pragma unroll
    for (int i = 0; i < NB; i++) acc += __ldg(&g_D0[i * D_ + d]) * wcol[i];
    float lam = g_poles[k + 1];
    g_UT[k * D_ + d] = acc * ALPHA_8 * rsqrtf(fmaxf(lam, 1e-20f));
}

// ------ 4) fused weights + secular, 2 timesteps/block <<<512,256>>> ------
__global__ void k_wsec(float* __restrict__ out) {
    __shared__ float smv0[D_], smv1[D_];
    __shared__ float zsh0[64], zsh1[64];
    __shared__ float red0[8], red1[8];
    __shared__ float w2s[2][NB], ds[NB], vals[2][NB];
    __shared__ float msqs[2];
    int bid = blockIdx.x, tid = threadIdx.x;
    int warp = tid >> 5, lane = tid & 31;
    int t0 = bid * 2;

    float mv0 = g_M[t0 * D_ + tid];
    float mv1 = g_M[(t0 + 1) * D_ + tid];
    smv0[tid] = mv0; smv1[tid] = mv1;
    float p0 = mv0 * mv0, p1 = mv1 * mv1;
#pragma unroll
    for (int o = 16; o > 0; o >>= 1) {
        p0 += __shfl_down_sync(0xFFFFFFFFu, p0, o);
        p1 += __shfl_down_sync(0xFFFFFFFFu, p1, o);
    }
    if (lane == 0) { red0[warp] = p0; red1[warp] = p1; }
    if (tid < NB) ds[tid] = g_poles[tid];
    __syncthreads();

    // z_k = U_k . m  (warp-per-k; UT row loaded once, used for both t)
#pragma unroll
    for (int it = 0; it < 8; it++) {
        int k = warp * 8 + it;
        if (k < 63) {
            float a0 = 0.f, a1 = 0.f;
#pragma unroll
            for (int j = 0; j < 8; j++) {
                float u = g_UT[k * D_ + lane + 32 * j];
                a0 += u * smv0[lane + 32 * j];
                a1 += u * smv1[lane + 32 * j];
            }
#pragma unroll
            for (int o = 16; o > 0; o >>= 1) {
                a0 += __shfl_down_sync(0xFFFFFFFFu, a0, o);
                a1 += __shfl_down_sync(0xFFFFFFFFu, a1, o);
            }
            if (lane == 0) { zsh0[k] = a0; zsh1[k] = a1; }
        }
    }
    __syncthreads();

    // weights: threads 0..63 -> t0, 64..127 -> t1
    if (tid == 0) {
        float msq = 0.f;
#pragma unroll
        for (int w = 0; w < 8; w++) msq += red0[w];
        float sz = 0.f;
        for (int k = 0; k < 63; k++) sz += zsh0[k] * zsh0[k];
        w2s[0][0] = fmaxf(msq - sz, 0.f);
        msqs[0] = msq;
    } else if (tid == 64) {
        float msq = 0.f;
#pragma unroll
        for (int w = 0; w < 8; w++) msq += red1[w];
        float sz = 0.f;
        for (int k = 0; k < 63; k++) sz += zsh1[k] * zsh1[k];
        w2s[1][0] = fmaxf(msq - sz, 0.f);
        msqs[1] = msq;
    } else if (tid < 64) {
        float z = zsh0[tid - 1];
        w2s[0][tid] = z * z;
    } else if (tid < 128) {
        int i = tid - 64;
        float z = zsh1[i - 1];
        w2s[1][i] = z * z;
    }
    __syncthreads();

    if (tid >= 128) return;   // past the last full barrier, safe to retire

    int sel = tid >> 6, i = tid & 63;
    float S = 0.f;
#pragma unroll 8
    for (int k = 0; k < NB; k++) S += w2s[sel][k];

    float lo = ds[i];
    float hi = (i < 63) ? ds[i + 1] : ds[63] + S;
    float lam = 0.5f * (lo + hi);

    for (int it = 0; it < NIT; it++) {
        float f = 1.f, fp = 0.f;
#pragma unroll 8
        for (int k = 0; k < NB; k++) {
            float diff = ds[k] - lam;
            float rc;
            asm("rcp.approx.f32 %0, %1;" : "=f"(rc) : "f"(diff));
            float term = w2s[sel][k] * rc;
            f  += term;
            fp += term * rc;
        }
        if (f > 0.f) hi = lam; else lo = lam;
        float ln = lam - __fdividef(f, fp);
        lam = (ln > lo && ln < hi) ? ln : 0.5f * (lo + hi);
    }

    float tr = msqs[sel] + g_trA;
    float v = fmaxf(__fdividef(lam, tr), EPSV);
    vals[sel][i] = v;
    __threadfence_block();
    asm volatile("bar.sync 1, 128;" ::: "memory");

    float ssum = 192.f * EPSV;
#pragma unroll 8
    for (int k = 0; k < NB; k++) ssum += vals[sel][k];
    float inv = __frcp_rn(ssum);

    float* o = out + (long)(t0 + sel) * D_;
    float ev = EPSV * inv;
    o[i]        = ev;               // positions   0..63  (zero eigs)
    o[i + 64]   = ev;               // positions  64..127
    o[i + 128]  = ev;               // positions 128..191
    o[i + 192]  = vals[sel][i] * inv;  // positions 192..255 (roots, ascending)
}

// ---------------- launcher ----------------
extern "C" void kernel_launch(void* const* d_in, const int* in_sizes, int n_in,
                              void* d_out, int out_size) {
    const int*   tokens = (const int*)d_in[0];
    const float* embed  = (const float*)d_in[1];
    const float* bubbles= (const float*)d_in[2];
    const float* mdecay = (const float*)d_in[3];
    float* out = (float*)d_out;

    cudaFuncSetAttribute(k_eigen, cudaFuncAttributeMaxDynamicSharedMemorySize,
                         66560);

    k_scan_gram<<<96, 256>>>(tokens, embed, bubbles, mdecay);
    k_eigen    <<<1, 1024, 66560>>>();
    k_buildU   <<<63, 256>>>();
    k_wsec     <<<512, 256>>>(out);
    (void)in_sizes; (void)n_in; (void)out_size;
}

// round 12
// speedup vs baseline: 1.2241x; 1.2241x over previous
#include <cuda_runtime.h>
#include <cuda_bf16.h>
#include <math.h>

#define D_    256
#define NB    64
#define SEQ   1024
#define EPSV  1e-10f
#define NIT   12
#define NROUNDS 7          // multisection rounds, 9x contraction each

// closed-form constants
#define ALPHA     0.32768f        // (1-2*ETA)^5
#define ALPHA2_64 0.0016777216f   // ALPHA^2 / 64
#define ALPHA_8   0.04096f        // ALPHA / 8
#define BETA      0.59049f        // (1-ETA)^5
#define OMBETA    0.40951f        // 1 - BETA

// ---------------- device scratch (no allocations allowed) ----------------
__device__ float g_D0[NB * D_];         // deviations
__device__ float g_Gg[NB * NB];         // Gram matrix
__device__ float g_V[62 * NB];          // Householder reflectors
__device__ float g_tau[64];             // reflector taus
__device__ float g_diag[NB];            // tridiag diagonal
__device__ float g_off[NB];             // tridiag off-diagonal
__device__ float g_Wg[NB * NB];         // eigenvectors of G (columns, ascending)
__device__ float g_UT[NB * D_];         // UT[k][d]: eigvec k of A (63 used)
__device__ float g_poles[NB];           // poles[0]=0, poles[1..63] ascending
__device__ float g_trA;                 // sum of kept poles
__device__ float g_M[SEQ * D_];         // m_t per step

// ------ 1) fused scan (32 blocks) + gram (64 blocks)  <<<96,256>>> -------
__global__ void k_scan_gram(const int* __restrict__ tokens,
                            const float* __restrict__ embed,
                            const float* __restrict__ bubbles,
                            const float* __restrict__ mdecay) {
    __shared__ float rowi[D_];
    __shared__ float bmsh[D_];
    __shared__ int   tk[128];
    int t = threadIdx.x;

    if (blockIdx.x < 64) {
        // ---- gram block i: G[i][*] = (a^2/64) D0_i . D0_j ----
        int i = blockIdx.x;
        float s = 0.f;
#pragma unroll 8
        for (int r = 0; r < NB; r++) s += bubbles[r * D_ + t];
        float bm = s * (1.f / NB);
        float v = bubbles[i * D_ + t] - bm;
        rowi[t] = v;
        bmsh[t] = bm;
        g_D0[i * D_ + t] = v;
        __syncthreads();

        int lane = t & 31, w = t >> 5;
#pragma unroll
        for (int it = 0; it < 8; it++) {
            int j = w * 8 + it;
            const float* bj = bubbles + j * D_;
            float acc = 0.f;
#pragma unroll
            for (int m = 0; m < 8; m++) {
                int d = lane + 32 * m;
                acc += rowi[d] * (bj[d] - bmsh[d]);
            }
#pragma unroll
            for (int o = 16; o > 0; o >>= 1)
                acc += __shfl_down_sync(0xFFFFFFFFu, acc, o);
            if (lane == 0) g_Gg[i * NB + j] = acc * ALPHA2_64;
        }
    } else {
        // ---- scan block: contraction a ~ 0.778, a^96 ~ 3e-11 warmup ----
        int c = blockIdx.x - 64, d = t;
        float s0 = 0.f, s1 = 0.f;
#pragma unroll 8
        for (int r = 0; r < NB; r += 2) {
            s0 += bubbles[r * D_ + d];
            s1 += bubbles[(r + 1) * D_ + d];
        }
        float cb = BETA * (s0 + s1) * (1.f / NB);
        float decay = 1.f / (1.f + expf(-mdecay[0]));
        float omdecay = 1.f - decay;

        int tout = c * 32;
        int tstart = tout - 96; if (tstart < 0) tstart = 0;
        int tend = tout + 32;
        int nwin = tend - tstart;
        if (d < nwin) tk[d] = tokens[tstart + d];
        __syncthreads();

        float mm = 0.f;
        float xs[8];
#pragma unroll
        for (int j = 0; j < 8; j++) xs[j] = embed[(long)tk[j] * D_ + d];
        for (int t0 = tstart; t0 < tend; t0 += 8) {
#pragma unroll
            for (int j = 0; j < 8; j++) {
                int tt = t0 + j;
                float x = xs[j];
                int tn = t0 + 8 + j;
                if (tn < tend) xs[j] = embed[(long)tk[tn - tstart] * D_ + d];
                float m = cb + OMBETA * (x + decay * mm);
                if (tt >= tout) g_M[tt * D_ + d] = m;
                mm = decay * mm + omdecay * m;
            }
        }
    }
}

// ------ 2) register-resident Householder tridiagonalization <<<1,64>>> ---
__global__ void __launch_bounds__(64) k_tridiag() {
    __shared__ float vsh[NB], wsh[NB], red2[2];
    __shared__ float x0sh;
    float row[NB];
    int r = threadIdx.x, lane = r & 31, warp = r >> 5;

#pragma unroll
    for (int c = 0; c < NB; c++) row[c] = g_Gg[r * NB + c];
    float x = row[0];

#pragma unroll 1
    for (int k = 0; k < 62; k++) {
        int n0 = k + 1;
        float xm = (r >= n0) ? x : 0.f;
        float s = xm * xm;
#pragma unroll
        for (int o = 16; o > 0; o >>= 1) s += __shfl_xor_sync(0xFFFFFFFFu, s, o);
        if (lane == 0) red2[warp] = s;
        if (r == n0) x0sh = xm;
        __syncthreads();
        float sum = red2[0] + red2[1];
        float x0 = x0sh;
        float sigma = sqrtf(sum);
        float sgn = (x0 >= 0.f) ? 1.f : -1.f;
        float tau = (sum > 1e-30f)
                  ? __fdividef(1.f, sigma * (sigma + fabsf(x0))) : 0.f;
        if (r == 0) { g_off[k] = -sgn * sigma; g_tau[k] = tau; }
        float v = (r == n0) ? x0 + sgn * sigma : xm;   // xm==0 for r<n0
        vsh[r] = v;
        g_V[k * NB + r] = v;
        __syncthreads();
        float a0 = 0.f, a1 = 0.f, a2 = 0.f, a3 = 0.f;
#pragma unroll
        for (int c = 0; c < NB; c += 4) {
            a0 += row[c]     * vsh[c];
            a1 += row[c + 1] * vsh[c + 1];
            a2 += row[c + 2] * vsh[c + 2];
            a3 += row[c + 3] * vsh[c + 3];
        }
        float p = tau * ((a0 + a1) + (a2 + a3));
        float pv = p * v;
#pragma unroll
        for (int o = 16; o > 0; o >>= 1) pv += __shfl_xor_sync(0xFFFFFFFFu, pv, o);
        if (lane == 0) red2[warp] = pv;
        __syncthreads();
        float K = 0.5f * tau * (red2[0] + red2[1]);
        float w = (r >= n0) ? (p - K * v) : 0.f;
        wsh[r] = w;
        __syncthreads();
        float xn = x;
#pragma unroll
        for (int c = 0; c < NB; c++) {
            float nv = row[c] - v * wsh[c] - w * vsh[c];
            row[c] = nv;
            if (c == n0) xn = nv;
        }
        x = xn;
    }

    float dg = 0.f;
#pragma unroll
    for (int c = 0; c < NB; c++) if (c == r) dg = row[c];
    g_diag[r] = dg;
    if (r == 63) g_off[62] = row[62];
    if (r == 0)  g_off[63] = 0.f;
}

// ------ 3) eigvecs: multisection Sturm + invit + backtransform -----------
__global__ void k_eigvec() {          // <<<1, 1024, 66560>>>
    extern __shared__ float sm[];
    float* E  = sm;                   // 64x65 eigvec columns
    float* DD = sm + 4160;            // invit scratch
    float* YY = sm + 8320;            // invit scratch
    float* V  = sm + 12480;           // reflectors [k][r], pitch 65

    __shared__ float diag[64], off[64], b2[64], eig[64], tauv[64];
    __shared__ float red[32];
    __shared__ int   oflag[64];
    __shared__ float sc_lo, sc_hi;

    int tid = threadIdx.x, lane = tid & 31, warp = tid >> 5;

    if (tid < 64) { diag[tid] = g_diag[tid]; off[tid] = g_off[tid]; }
    if (tid < 62) tauv[tid] = g_tau[tid];
    for (int e = tid; e < 62 * NB; e += 1024)
        V[(e >> 6) * 65 + (e & 63)] = g_V[e];
    __syncthreads();
    if (tid < 63) b2[tid] = off[tid] * off[tid];
    if (tid == 0) {
        float lo = 1e30f, hi = -1e30f;
        for (int i = 0; i < 64; i++) {
            float om = (i > 0) ? fabsf(off[i - 1]) : 0.f;
            float op = (i < 63) ? fabsf(off[i]) : 0.f;
            lo = fminf(lo, diag[i] - om - op);
            hi = fmaxf(hi, diag[i] + om + op);
        }
        float mg = 1e-6f * fmaxf(fabsf(lo), fabsf(hi)) + 1e-30f;
        sc_lo = lo - mg; sc_hi = hi + mg;
    }
    __syncthreads();

    // ---- multisection Sturm: 8 threads per eigenvalue ----
    if (tid < 512) {
        int i = tid >> 3, s8 = tid & 7;
        float lo = sc_lo, hi = sc_hi;
        for (int round = 0; round < NROUNDS; round++) {
            float step = (hi - lo) * (1.f / 9.f);
            float mid = lo + step * (float)(s8 + 1);
            float d = diag[0] - mid;
            int cnt = (d < 0.f);
            for (int j = 1; j < 64; j++) {
                float dg = (fabsf(d) < 1e-25f) ? -1e-25f : d;
                d = (diag[j] - mid) - __fdividef(b2[j - 1], dg);
                cnt += (d < 0.f);
            }
            unsigned bal = __ballot_sync(0xFFFFFFFFu, cnt <= i);
            unsigned bits = (bal >> (lane & 24)) & 0xFFu;
            int p = __popc(bits);
            lo = lo + step * (float)p;
            hi = lo + step;
        }
        if (s8 == 0) eig[i] = 0.5f * (lo + hi);
    }
    __syncthreads();

    // ---- inverse iteration ----
    if (tid < 64) {
        int i = tid;
        float scale = fmaxf(fabsf(sc_hi), fabsf(sc_lo));
        float lam = eig[i] + scale * 2e-6f;
        unsigned h = (unsigned)(i * 2654435761u) ^ 0x9E3779B9u;
        for (int j = 0; j < 64; j++) {
            h = h * 1664525u + 1013904223u;
            E[j * 65 + i] = 1.f + (float)(h >> 16) * 1.52587890625e-05f;
        }
        for (int iter = 0; iter < 3; iter++) {
            float dprev = diag[0] - lam;
            dprev = (fabsf(dprev) < 1e-20f) ? copysignf(1e-20f, dprev) : dprev;
            DD[i * 65 + 0] = dprev;
            float yprev = E[0 * 65 + i];
            YY[i * 65 + 0] = yprev;
            for (int j = 1; j < 64; j++) {
                float m = __fdividef(off[j - 1], dprev);
                float dcur = (diag[j] - lam) - m * off[j - 1];
                dcur = (fabsf(dcur) < 1e-20f) ? copysignf(1e-20f, dcur) : dcur;
                float ycur = E[j * 65 + i] - m * yprev;
                DD[i * 65 + j] = dcur;
                YY[i * 65 + j] = ycur;
                dprev = dcur; yprev = ycur;
            }
            float vj = __fdividef(YY[i * 65 + 63], DD[i * 65 + 63]);
            E[63 * 65 + i] = vj;
            float nrm = vj * vj;
            for (int j = 62; j >= 0; j--) {
                vj = __fdividef(YY[i * 65 + j] - off[j] * vj, DD[i * 65 + j]);
                E[j * 65 + i] = vj;
                nrm += vj * vj;
            }
            float inv = rsqrtf(nrm);
            for (int j = 0; j < 64; j++) E[j * 65 + i] *= inv;
        }
    }
    __syncthreads();

    // ---- gap-flagged neighbor re-orthogonalization ----
    if (tid < 64) {
        float scale = fmaxf(fabsf(eig[63]), fabsf(eig[0]));
        oflag[tid] = (tid > 0) && (eig[tid] - eig[tid - 1] < 1e-3f * scale);
    }
    __syncthreads();
    for (int i = 1; i < 64; i++) {
        if (!oflag[i]) continue;
        float pr = (tid < 64) ? E[tid * 65 + i] * E[tid * 65 + i - 1] : 0.f;
#pragma unroll
        for (int o = 16; o > 0; o >>= 1)
            pr += __shfl_down_sync(0xFFFFFFFFu, pr, o);
        if (lane == 0 && tid < 64) red[warp] = pr;
        __syncthreads();
        float dot = red[0] + red[1];
        float nv = 0.f;
        if (tid < 64) {
            E[tid * 65 + i] -= dot * E[tid * 65 + i - 1];
            nv = E[tid * 65 + i] * E[tid * 65 + i];
        }
#pragma unroll
        for (int o = 16; o > 0; o >>= 1)
            nv += __shfl_down_sync(0xFFFFFFFFu, nv, o);
        if (lane == 0 && tid < 64) red[warp] = nv;
        __syncthreads();
        float sc = rsqrtf(red[0] + red[1] + 1e-30f);
        if (tid < 64) E[tid * 65 + i] *= sc;
        __syncthreads();
    }

    // ---- back-transform: apply reflectors k = 61..0 (cols independent) --
    {
        int col = tid >> 4, sub = tid & 15;
        for (int k = 61; k >= 0; k--) {
            int n0 = k + 1, n2 = 63 - k;
            float tau = tauv[k];
            float acc = 0.f;
            for (int r = sub; r < n2; r += 16)
                acc += V[k * 65 + n0 + r] * E[(n0 + r) * 65 + col];
#pragma unroll
            for (int o = 8; o > 0; o >>= 1)
                acc += __shfl_xor_sync(0xFFFFFFFFu, acc, o, 16);
            float w = tau * acc;
            for (int r = sub; r < n2; r += 16)
                E[(n0 + r) * 65 + col] -= w * V[k * 65 + n0 + r];
        }
    }
    __syncthreads();

    if (tid == 0) {
        g_poles[0] = 0.f;
        float s = 0.f;
        for (int k = 1; k < 64; k++) {
            float p = fmaxf(eig[k], 1e-12f);
            g_poles[k] = p;
            s += p;
        }
        g_trA = s;
    }
    for (int e = tid; e < NB * NB; e += 1024)
        g_Wg[e] = E[(e >> 6) * 65 + (e & 63)];
}

// ------ 4) build U^T  <<<63,256>>>  (full unroll -> deep MLP) ------------
__global__ void k_buildU() {
    __shared__ float wcol[NB];
    int k = blockIdx.x, d = threadIdx.x;
    if (d < NB) wcol[d] = g_Wg[d * NB + (k + 1)];   // ascending columns
    __syncthreads();
    float acc = 0.f;
#pragma unroll
    for (int i = 0; i < NB; i++) acc += __ldg(&g_D0[i * D_ + d]) * wcol[i];
    float lam = g_poles[k + 1];
    g_UT[k * D_ + d] = acc * ALPHA_8 * rsqrtf(fmaxf(lam, 1e-20f));
}

// ------ 5) fused weights + secular, 4 timesteps/block <<<256,256>>> ------
// secular phase occupies all 256 threads (4 x 64 roots); (pole,w2) packed
// as float2 so the inner loop does one LDS.64 per pole.
__global__ void k_wsec(float* __restrict__ out) {
    __shared__ float  smv[4][D_];
    __shared__ float  zsh[4][64];
    __shared__ float  redp[4][8];
    __shared__ float2 dw[4][NB];
    __shared__ float  vals[4][NB];
    __shared__ float  msqs[4];
    int bid = blockIdx.x, tid = threadIdx.x;
    int warp = tid >> 5, lane = tid & 31;
    int t0 = bid * 4;

    float mv[4];
#pragma unroll
    for (int q = 0; q < 4; q++) {
        mv[q] = g_M[(t0 + q) * D_ + tid];
        smv[q][tid] = mv[q];
    }
#pragma unroll
    for (int q = 0; q < 4; q++) {
        float p = mv[q] * mv[q];
#pragma unroll
        for (int o = 16; o > 0; o >>= 1)
            p += __shfl_down_sync(0xFFFFFFFFu, p, o);
        if (lane == 0) redp[q][warp] = p;
    }
    __syncthreads();

    // z_k = U_k . m  (warp-per-k; UT row loaded once, reused for 4 t's)
#pragma unroll
    for (int it = 0; it < 8; it++) {
        int k = warp * 8 + it;
        if (k < 63) {
            float a0 = 0.f, a1 = 0.f, a2 = 0.f, a3 = 0.f;
#pragma unroll
            for (int j = 0; j < 8; j++) {
                int d = lane + 32 * j;
                float u = g_UT[k * D_ + d];
                a0 += u * smv[0][d];
                a1 += u * smv[1][d];
                a2 += u * smv[2][d];
                a3 += u * smv[3][d];
            }
#pragma unroll
            for (int o = 16; o > 0; o >>= 1) {
                a0 += __shfl_down_sync(0xFFFFFFFFu, a0, o);
                a1 += __shfl_down_sync(0xFFFFFFFFu, a1, o);
                a2 += __shfl_down_sync(0xFFFFFFFFu, a2, o);
                a3 += __shfl_down_sync(0xFFFFFFFFu, a3, o);
            }
            if (lane == 0) {
                zsh[0][k] = a0; zsh[1][k] = a1;
                zsh[2][k] = a2; zsh[3][k] = a3;
            }
        }
    }
    __syncthreads();

    // weights: thread (sel*64 + i) fills dw[sel][i]
    {
        int sel = tid >> 6, i = tid & 63;
        if (i == 0) {
            float msq = 0.f;
#pragma unroll
            for (int w = 0; w < 8; w++) msq += redp[sel][w];
            float sz = 0.f;
            for (int k = 0; k < 63; k++) sz += zsh[sel][k] * zsh[sel][k];
            dw[sel][0] = make_float2(g_poles[0], fmaxf(msq - sz, 0.f));
            msqs[sel] = msq;
        } else {
            float z = zsh[sel][i - 1];
            dw[sel][i] = make_float2(g_poles[i], z * z);
        }
    }
    __syncthreads();

    int sel = tid >> 6, i = tid & 63;
    float S = 0.f;
#pragma unroll 8
    for (int k = 0; k < NB; k++) S += dw[sel][k].y;

    float lo = dw[sel][i].x;
    float hi = (i < 63) ? dw[sel][i + 1].x : dw[sel][63].x + S;
    float lam = 0.5f * (lo + hi);

    for (int it = 0; it < NIT; it++) {
        float f = 1.f, fp = 0.f;
#pragma unroll 8
        for (int k = 0; k < NB; k++) {
            float2 p = dw[sel][k];
            float diff = p.x - lam;
            float rc;
            asm("rcp.approx.f32 %0, %1;" : "=f"(rc) : "f"(diff));
            float term = p.y * rc;
            f  += term;
            fp += term * rc;
        }
        if (f > 0.f) hi = lam; else lo = lam;
        float ln = lam - __fdividef(f, fp);
        lam = (ln > lo && ln < hi) ? ln : 0.5f * (lo + hi);
    }

    float tr = msqs[sel] + g_trA;
    float v = fmaxf(__fdividef(lam, tr), EPSV);
    vals[sel][i] = v;
    __syncthreads();

    float ssum = 192.f * EPSV;
#pragma unroll 8
    for (int k = 0; k < NB; k++) ssum += vals[sel][k];
    float inv = __frcp_rn(ssum);

    float* o = out + (long)(t0 + sel) * D_;
    float ev = EPSV * inv;
    o[i]        = ev;               // positions   0..63  (zero eigs)
    o[i + 64]   = ev;               // positions  64..127
    o[i + 128]  = ev;               // positions 128..191
    o[i + 192]  = vals[sel][i] * inv;  // positions 192..255 (roots, ascending)
}

// ---------------- launcher ----------------
extern "C" void kernel_launch(void* const* d_in, const int* in_sizes, int n_in,
                              void* d_out, int out_size) {
    const int*   tokens = (const int*)d_in[0];
    const float* embed  = (const float*)d_in[1];
    const float* bubbles= (const float*)d_in[2];
    const float* mdecay = (const float*)d_in[3];
    float* out = (float*)d_out;

    cudaFuncSetAttribute(k_eigvec, cudaFuncAttributeMaxDynamicSharedMemorySize,
                         66560);

    k_scan_gram<<<96, 256>>>(tokens, embed, bubbles, mdecay);
    k_tridiag  <<<1, 64>>>();
    k_eigvec   <<<1, 1024, 66560>>>();
    k_buildU   <<<63, 256>>>();
    k_wsec     <<<256, 256>>>(out);
    (void)in_sizes; (void)n_in; (void)out_size;
}